// round 1
// baseline (speedup 1.0000x reference)
#include <cuda_runtime.h>

#define N_NODES 32768
#define N_EDGES 524288
#define NH      4
#define HDIM    128
#define HD      512      // NH*HDIM
#define HID_    128
#define DFF_    2048
#define SLOPE_  0.2f
#define EPS_    1e-5f

// ---------------- scratch (device globals; no allocation allowed) ----------
__device__ float    g_ft [N_NODES*HD];      // ft = h @ W_fc            (64MB)
__device__ float    g_res[N_NODES*HD];      // res = h@W_res, later g   (64MB)
__device__ float    g_el [N_NODES*NH];
__device__ float    g_er [N_NODES*NH];
__device__ float    g_sc [N_EDGES*NH];      // scores, then exp-weights (8MB)
__device__ unsigned g_menc[N_NODES*NH];     // encoded segment max
__device__ float    g_z  [N_NODES*NH];      // softmax denominators
__device__ int      g_deg[N_NODES];
__device__ int      g_cursor[N_NODES];
__device__ int      g_rowptr[N_NODES+1];
__device__ int      g_eix[N_EDGES];         // CSR edge indices by dst
__device__ float    g_x1 [N_NODES*HID_];    // post-LN1

// ordered-float encoding for atomicMax on unsigned
__device__ __forceinline__ unsigned fenc(float f){
    unsigned u = __float_as_uint(f);
    return (u & 0x80000000u) ? ~u : (u | 0x80000000u);
}
__device__ __forceinline__ float fdec(unsigned k){
    return (k & 0x80000000u) ? __uint_as_float(k & 0x7fffffffu)
                             : __uint_as_float(~k);
}

// ---------------- init: zero per-call state --------------------------------
__global__ void k_init(){
    int i = blockIdx.x*256 + threadIdx.x;   // 512*256 = 131072 = N*NH
    g_z[i]    = 0.f;
    g_menc[i] = 0u;                         // < encode of any finite float
    if (i < N_NODES){ g_deg[i] = 0; g_cursor[i] = 0; }
}

// ---------------- GEMM A: C[N,512] = h[N,128] @ W[128,512] (z: fc / res) ---
__global__ __launch_bounds__(256) void k_gemmA(const float* __restrict__ h,
        const float* __restrict__ Wfc, const float* __restrict__ Wres){
    __shared__ float As[32][136];   // [k][r]
    __shared__ float Bs[32][136];   // [k][c]
    const float* __restrict__ W = blockIdx.z ? Wres : Wfc;
    float* __restrict__ C = blockIdx.z ? g_res : g_ft;
    const int row0 = blockIdx.x*128, col0 = blockIdx.y*128;
    const int tid = threadIdx.x, tx = tid & 15, ty = tid >> 4;
    float acc[8][8];
    #pragma unroll
    for (int i=0;i<8;i++)
        #pragma unroll
        for (int j=0;j<8;j++) acc[i][j]=0.f;

    for (int kc=0; kc<HID_; kc+=32){
        #pragma unroll
        for (int j=0;j<4;j++){
            int s = tid + 256*j; int r = s>>3, kq = s&7;
            float4 v = *(const float4*)&h[(row0+r)*HID_ + kc + kq*4];
            As[kq*4+0][r]=v.x; As[kq*4+1][r]=v.y; As[kq*4+2][r]=v.z; As[kq*4+3][r]=v.w;
        }
        #pragma unroll
        for (int j=0;j<4;j++){
            int s = tid + 256*j; int k = s>>5, cq = s&31;
            *(float4*)&Bs[k][cq*4] = *(const float4*)&W[(kc+k)*HD + col0 + cq*4];
        }
        __syncthreads();
        #pragma unroll
        for (int k=0;k<32;k++){
            float a[8], b[8];
            *(float4*)&a[0] = *(float4*)&As[k][ty*8];
            *(float4*)&a[4] = *(float4*)&As[k][ty*8+4];
            *(float4*)&b[0] = *(float4*)&Bs[k][tx*8];
            *(float4*)&b[4] = *(float4*)&Bs[k][tx*8+4];
            #pragma unroll
            for (int i=0;i<8;i++)
                #pragma unroll
                for (int j=0;j<8;j++) acc[i][j] = fmaf(a[i], b[j], acc[i][j]);
        }
        __syncthreads();
    }
    #pragma unroll
    for (int i=0;i<8;i++){
        int row = row0 + ty*8 + i;
        float4 v0 = make_float4(acc[i][0],acc[i][1],acc[i][2],acc[i][3]);
        float4 v1 = make_float4(acc[i][4],acc[i][5],acc[i][6],acc[i][7]);
        *(float4*)&C[row*HD + col0 + tx*8    ] = v0;
        *(float4*)&C[row*HD + col0 + tx*8 + 4] = v1;
    }
}

// ---------------- el/er: per (node,head) dot with attn vectors -------------
__global__ __launch_bounds__(256) void k_eler(const float* __restrict__ attn_l,
                                              const float* __restrict__ attn_r){
    int wid = threadIdx.x>>5, lane = threadIdx.x&31;
    int gw = blockIdx.x*8 + wid;            // < N*NH
    int n = gw>>2, hh = gw&3;
    const float4* ft4 = (const float4*)g_ft;
    float4 x  = ft4[n*128 + hh*32 + lane];
    float4 al = ((const float4*)attn_l)[hh*32+lane];
    float4 ar = ((const float4*)attn_r)[hh*32+lane];
    float pl = x.x*al.x + x.y*al.y + x.z*al.z + x.w*al.w;
    float pr = x.x*ar.x + x.y*ar.y + x.z*ar.z + x.w*ar.w;
    #pragma unroll
    for (int off=16; off; off>>=1){
        pl += __shfl_xor_sync(0xffffffffu, pl, off);
        pr += __shfl_xor_sync(0xffffffffu, pr, off);
    }
    if (lane==0){ g_el[n*NH+hh]=pl; g_er[n*NH+hh]=pr; }
}

// ---------------- edge pass 1: scores, segment max, degrees ----------------
__global__ __launch_bounds__(256) void k_edge1(const float* __restrict__ e,
        const int* __restrict__ src, const int* __restrict__ dst,
        const float* __restrict__ W_fe, const float* __restrict__ attn_e){
    __shared__ float ce[NH];
    int wid = threadIdx.x>>5, lane = threadIdx.x&31;
    if (wid < NH){
        float p = 0.f;
        #pragma unroll
        for (int q=0;q<4;q++){
            int d = lane + q*32;
            p += W_fe[wid*HDIM+d]*attn_e[wid*HDIM+d];
        }
        #pragma unroll
        for (int off=16; off; off>>=1) p += __shfl_xor_sync(0xffffffffu, p, off);
        if (lane==0) ce[wid]=p;
    }
    __syncthreads();
    int ei = blockIdx.x*256 + threadIdx.x;
    if (ei >= N_EDGES) return;
    int s = src[ei], d = dst[ei];
    float ev = e[ei];
    float4 els = ((const float4*)g_el)[s];
    float4 erd = ((const float4*)g_er)[d];
    float sc[4];
    sc[0] = els.x + erd.x + ev*ce[0];
    sc[1] = els.y + erd.y + ev*ce[1];
    sc[2] = els.z + erd.z + ev*ce[2];
    sc[3] = els.w + erd.w + ev*ce[3];
    #pragma unroll
    for (int hh=0;hh<4;hh++){
        float v = sc[hh];
        v = v > 0.f ? v : SLOPE_*v;
        sc[hh] = v;
        atomicMax(&g_menc[d*NH+hh], fenc(v));
    }
    *(float4*)&g_sc[ei*4] = make_float4(sc[0],sc[1],sc[2],sc[3]);
    atomicAdd(&g_deg[d], 1);
}

// ---------------- edge pass 2: exp weights + denominators ------------------
__global__ __launch_bounds__(256) void k_edge2(const int* __restrict__ dst){
    int ei = blockIdx.x*256 + threadIdx.x;
    if (ei >= N_EDGES) return;
    int d = dst[ei];
    uint4 mk = *(const uint4*)&g_menc[d*4];
    float4 sv = *(const float4*)&g_sc[ei*4];
    float w0 = expf(sv.x - fdec(mk.x));
    float w1 = expf(sv.y - fdec(mk.y));
    float w2 = expf(sv.z - fdec(mk.z));
    float w3 = expf(sv.w - fdec(mk.w));
    *(float4*)&g_sc[ei*4] = make_float4(w0,w1,w2,w3);
    atomicAdd(&g_z[d*4+0], w0);
    atomicAdd(&g_z[d*4+1], w1);
    atomicAdd(&g_z[d*4+2], w2);
    atomicAdd(&g_z[d*4+3], w3);
}

// ---------------- CSR scan (single block) ----------------------------------
__global__ __launch_bounds__(1024) void k_scan(){
    __shared__ int sm[1024];
    int t = threadIdx.x;
    int base = t*32;
    int s = 0;
    #pragma unroll
    for (int i=0;i<32;i++) s += g_deg[base+i];
    sm[t]=s; __syncthreads();
    for (int off=1; off<1024; off<<=1){
        int v = (t>=off)? sm[t-off] : 0;
        __syncthreads();
        if (t>=off) sm[t]+=v;
        __syncthreads();
    }
    int run = sm[t]-s;       // exclusive
    for (int i=0;i<32;i++){ g_rowptr[base+i]=run; run += g_deg[base+i]; }
    if (t==1023) g_rowptr[N_NODES]=run;
}

__global__ __launch_bounds__(256) void k_fill(const int* __restrict__ dst){
    int ei = blockIdx.x*256 + threadIdx.x;
    if (ei >= N_EDGES) return;
    int d = dst[ei];
    int pos = atomicAdd(&g_cursor[d], 1);
    g_eix[g_rowptr[d]+pos] = ei;
}

// ---------------- aggregation: warp per (node,head) ------------------------
__global__ __launch_bounds__(256) void k_agg(const int* __restrict__ src,
                                             const float* __restrict__ gat_bias){
    int wid = threadIdx.x>>5, lane = threadIdx.x&31;
    int gw = blockIdx.x*8 + wid;
    int n = gw>>2, hh = gw&3;
    int beg = g_rowptr[n], end = g_rowptr[n+1];
    float zz = g_z[n*NH+hh];
    float zi = zz > 0.f ? 1.f/zz : 1.f;
    float4 acc = make_float4(0,0,0,0);
    const float4* ft4 = (const float4*)g_ft;
    for (int i=beg; i<end; i++){
        int ee = g_eix[i];
        float w = g_sc[ee*4+hh];
        int s = src[ee];
        float4 v = ft4[s*128 + hh*32 + lane];
        acc.x = fmaf(w, v.x, acc.x);
        acc.y = fmaf(w, v.y, acc.y);
        acc.z = fmaf(w, v.z, acc.z);
        acc.w = fmaf(w, v.w, acc.w);
    }
    int base = n*HD + hh*HDIM + lane*4;
    float4 r  = *(const float4*)&g_res[base];
    float4 bv = *(const float4*)&gat_bias[hh*HDIM + lane*4];
    float4 o;
    o.x = fmaxf(acc.x*zi + r.x + bv.x, 0.f);
    o.y = fmaxf(acc.y*zi + r.y + bv.y, 0.f);
    o.z = fmaxf(acc.z*zi + r.z + bv.z, 0.f);
    o.w = fmaxf(acc.w*zi + r.w + bv.w, 0.f);
    *(float4*)&g_res[base] = o;   // g_res becomes g = relu(rst)
}

// ---------------- MHA GEMM + relu + residual + LN1 -------------------------
__global__ __launch_bounds__(256) void k_mha(const float* __restrict__ Wm,
        const float* __restrict__ bm, const float* __restrict__ h0,
        const float* __restrict__ g1, const float* __restrict__ be1){
    __shared__ float As[32][136];
    __shared__ float Bs[32][136];
    const int row0 = blockIdx.x*128;
    const int tid = threadIdx.x, tx = tid & 15, ty = tid >> 4;
    float acc[8][8];
    #pragma unroll
    for (int i=0;i<8;i++)
        #pragma unroll
        for (int j=0;j<8;j++) acc[i][j]=0.f;

    for (int kc=0; kc<HD; kc+=32){
        #pragma unroll
        for (int j=0;j<4;j++){
            int s = tid + 256*j; int r = s>>3, kq = s&7;
            float4 v = *(const float4*)&g_res[(row0+r)*HD + kc + kq*4];
            As[kq*4+0][r]=v.x; As[kq*4+1][r]=v.y; As[kq*4+2][r]=v.z; As[kq*4+3][r]=v.w;
        }
        #pragma unroll
        for (int j=0;j<4;j++){
            int s = tid + 256*j; int k = s>>5, cq = s&31;
            *(float4*)&Bs[k][cq*4] = *(const float4*)&Wm[(kc+k)*HID_ + cq*4];
        }
        __syncthreads();
        #pragma unroll
        for (int k=0;k<32;k++){
            float a[8], b[8];
            *(float4*)&a[0] = *(float4*)&As[k][ty*8];
            *(float4*)&a[4] = *(float4*)&As[k][ty*8+4];
            *(float4*)&b[0] = *(float4*)&Bs[k][tx*8];
            *(float4*)&b[4] = *(float4*)&Bs[k][tx*8+4];
            #pragma unroll
            for (int i=0;i<8;i++)
                #pragma unroll
                for (int j=0;j<8;j++) acc[i][j] = fmaf(a[i], b[j], acc[i][j]);
        }
        __syncthreads();
    }
    // epilogue: +bias, relu, +h0, LayerNorm over 128 cols (16-thread groups)
    #pragma unroll
    for (int i=0;i<8;i++){
        int row = row0 + ty*8 + i;
        float v[8], s1=0.f, s2=0.f;
        #pragma unroll
        for (int j=0;j<8;j++){
            int col = tx*8+j;
            float t = acc[i][j] + bm[col];
            t = fmaxf(t, 0.f);
            t += h0[row*HID_+col];
            v[j]=t; s1+=t; s2+=t*t;
        }
        #pragma unroll
        for (int off=8; off; off>>=1){
            s1 += __shfl_xor_sync(0xffffffffu, s1, off, 16);
            s2 += __shfl_xor_sync(0xffffffffu, s2, off, 16);
        }
        float mean = s1*(1.f/HID_);
        float var  = s2*(1.f/HID_) - mean*mean;
        float rs   = rsqrtf(var + EPS_);
        #pragma unroll
        for (int j=0;j<8;j++){
            int col = tx*8+j;
            g_x1[row*HID_+col] = (v[j]-mean)*rs*g1[col] + be1[col];
        }
    }
}

// ---------------- fused FFN + residual + LN2 -------------------------------
// block: 64 rows x 128 cols, K chunked by 64; dyn smem ~117KB
__global__ __launch_bounds__(256) void k_ffn(const float* __restrict__ W1,
        const float* __restrict__ b1v, const float* __restrict__ W2,
        const float* __restrict__ b2v, const float* __restrict__ g2,
        const float* __restrict__ be2, float* __restrict__ out){
    extern __shared__ float sm[];
    float* xs   = sm;            // 64*132  = 8448
    float* W1c  = sm + 8448;     // 128*68  = 8704
    float* midS = sm + 17152;    // 64*68   = 4352
    float* W2c  = sm + 21504;    // 64*132  = 8448  -> total 29952 floats
    const int tid = threadIdx.x, tx = tid & 15, ty = tid >> 4;
    const int row0 = blockIdx.x*64;

    #pragma unroll
    for (int j=0;j<8;j++){
        int s = tid + 256*j; int r = s>>5, cq = s&31;
        *(float4*)&xs[r*132 + cq*4] = *(const float4*)&g_x1[(row0+r)*HID_ + cq*4];
    }
    float acc[4][8];
    #pragma unroll
    for (int i=0;i<4;i++)
        #pragma unroll
        for (int j=0;j<8;j++) acc[i][j]=0.f;

    for (int c0=0; c0<DFF_; c0+=64){
        __syncthreads();   // protect W1c/W2c/midS overwrite vs previous reads
        #pragma unroll
        for (int j=0;j<8;j++){
            int s = tid + 256*j; int k = s>>4, cq = s&15;
            *(float4*)&W1c[k*68 + cq*4] = *(const float4*)&W1[k*DFF_ + c0 + cq*4];
        }
        #pragma unroll
        for (int j=0;j<8;j++){
            int s = tid + 256*j; int k = s>>5, cq = s&31;
            *(float4*)&W2c[k*132 + cq*4] = *(const float4*)&W2[(c0+k)*HID_ + cq*4];
        }
        __syncthreads();
        // mid[64x64] = xs[64x128] @ W1c[128x64]
        float mm[4][4];
        #pragma unroll
        for (int i=0;i<4;i++)
            #pragma unroll
            for (int j=0;j<4;j++) mm[i][j]=0.f;
        #pragma unroll 8
        for (int k=0;k<128;k++){
            float4 bv = *(const float4*)&W1c[k*68 + tx*4];
            float a0 = xs[(ty*4+0)*132 + k];
            float a1 = xs[(ty*4+1)*132 + k];
            float a2 = xs[(ty*4+2)*132 + k];
            float a3 = xs[(ty*4+3)*132 + k];
            mm[0][0]=fmaf(a0,bv.x,mm[0][0]); mm[0][1]=fmaf(a0,bv.y,mm[0][1]);
            mm[0][2]=fmaf(a0,bv.z,mm[0][2]); mm[0][3]=fmaf(a0,bv.w,mm[0][3]);
            mm[1][0]=fmaf(a1,bv.x,mm[1][0]); mm[1][1]=fmaf(a1,bv.y,mm[1][1]);
            mm[1][2]=fmaf(a1,bv.z,mm[1][2]); mm[1][3]=fmaf(a1,bv.w,mm[1][3]);
            mm[2][0]=fmaf(a2,bv.x,mm[2][0]); mm[2][1]=fmaf(a2,bv.y,mm[2][1]);
            mm[2][2]=fmaf(a2,bv.z,mm[2][2]); mm[2][3]=fmaf(a2,bv.w,mm[2][3]);
            mm[3][0]=fmaf(a3,bv.x,mm[3][0]); mm[3][1]=fmaf(a3,bv.y,mm[3][1]);
            mm[3][2]=fmaf(a3,bv.z,mm[3][2]); mm[3][3]=fmaf(a3,bv.w,mm[3][3]);
        }
        // +b1, relu, stage
        #pragma unroll
        for (int i=0;i<4;i++){
            float4 w;
            w.x = fmaxf(mm[i][0] + b1v[c0 + tx*4 + 0], 0.f);
            w.y = fmaxf(mm[i][1] + b1v[c0 + tx*4 + 1], 0.f);
            w.z = fmaxf(mm[i][2] + b1v[c0 + tx*4 + 2], 0.f);
            w.w = fmaxf(mm[i][3] + b1v[c0 + tx*4 + 3], 0.f);
            *(float4*)&midS[(ty*4+i)*68 + tx*4] = w;
        }
        __syncthreads();
        // acc[64x128] += midS[64x64] @ W2c[64x128]
        #pragma unroll 8
        for (int k=0;k<64;k++){
            float4 b0 = *(const float4*)&W2c[k*132 + tx*8];
            float4 b1_ = *(const float4*)&W2c[k*132 + tx*8 + 4];
            #pragma unroll
            for (int i=0;i<4;i++){
                float a = midS[(ty*4+i)*68 + k];
                acc[i][0]=fmaf(a,b0.x,acc[i][0]); acc[i][1]=fmaf(a,b0.y,acc[i][1]);
                acc[i][2]=fmaf(a,b0.z,acc[i][2]); acc[i][3]=fmaf(a,b0.w,acc[i][3]);
                acc[i][4]=fmaf(a,b1_.x,acc[i][4]); acc[i][5]=fmaf(a,b1_.y,acc[i][5]);
                acc[i][6]=fmaf(a,b1_.z,acc[i][6]); acc[i][7]=fmaf(a,b1_.w,acc[i][7]);
            }
        }
    }
    // epilogue: +b2, +x1 residual, LN over 128 cols, write out
    #pragma unroll
    for (int i=0;i<4;i++){
        int r = ty*4+i, row = row0 + r;
        float v[8], s1=0.f, s2=0.f;
        #pragma unroll
        for (int j=0;j<8;j++){
            int col = tx*8+j;
            float t = acc[i][j] + b2v[col] + xs[r*132 + col];
            v[j]=t; s1+=t; s2+=t*t;
        }
        #pragma unroll
        for (int off=8; off; off>>=1){
            s1 += __shfl_xor_sync(0xffffffffu, s1, off, 16);
            s2 += __shfl_xor_sync(0xffffffffu, s2, off, 16);
        }
        float mean = s1*(1.f/HID_);
        float var  = s2*(1.f/HID_) - mean*mean;
        float rs   = rsqrtf(var + EPS_);
        #pragma unroll
        for (int j=0;j<8;j++){
            int col = tx*8+j;
            out[row*HID_+col] = (v[j]-mean)*rs*g2[col] + be2[col];
        }
    }
}

// ---------------- launch ----------------------------------------------------
extern "C" void kernel_launch(void* const* d_in, const int* in_sizes, int n_in,
                              void* d_out, int out_size){
    // batch_size may or may not appear as input #4 (scalar). Detect by size.
    int o = (in_sizes[4] == 1) ? 1 : 0;
    const float* h       = (const float*)d_in[0];
    const float* e       = (const float*)d_in[1];
    const int*   src     = (const int*)  d_in[2];
    const int*   dst     = (const int*)  d_in[3];
    const float* W_fc    = (const float*)d_in[4+o];
    const float* attn_l  = (const float*)d_in[5+o];
    const float* attn_r  = (const float*)d_in[6+o];
    const float* W_fe    = (const float*)d_in[7+o];
    const float* attn_e  = (const float*)d_in[8+o];
    const float* W_res   = (const float*)d_in[9+o];
    const float* gatb    = (const float*)d_in[10+o];
    const float* W_mha   = (const float*)d_in[11+o];
    const float* b_mha   = (const float*)d_in[12+o];
    const float* n1_g    = (const float*)d_in[13+o];
    const float* n1_b    = (const float*)d_in[14+o];
    const float* n2_g    = (const float*)d_in[15+o];
    const float* n2_b    = (const float*)d_in[16+o];
    const float* W1      = (const float*)d_in[17+o];
    const float* b1      = (const float*)d_in[18+o];
    const float* W2      = (const float*)d_in[19+o];
    const float* b2      = (const float*)d_in[20+o];
    float* out = (float*)d_out;

    cudaFuncSetAttribute(k_ffn, cudaFuncAttributeMaxDynamicSharedMemorySize,
                         29952*sizeof(float));

    k_init<<<512,256>>>();
    dim3 gA(N_NODES/128, HD/128, 2);
    k_gemmA<<<gA,256>>>(h, W_fc, W_res);
    k_eler<<<N_NODES*NH/8,256>>>(attn_l, attn_r);
    k_edge1<<<N_EDGES/256,256>>>(e, src, dst, W_fe, attn_e);
    k_edge2<<<N_EDGES/256,256>>>(dst);
    k_scan<<<1,1024>>>();
    k_fill<<<N_EDGES/256,256>>>(dst);
    k_agg<<<N_NODES*NH/8,256>>>(src, gatb);
    k_mha<<<N_NODES/128,256>>>(W_mha, b_mha, h, n1_g, n1_b);
    k_ffn<<<N_NODES/64,256,29952*sizeof(float)>>>(W1, b1, W2, b2, n2_g, n2_b, out);
}

// round 3
// speedup vs baseline: 1.8156x; 1.8156x over previous
#include <cuda_runtime.h>
#include <cuda_bf16.h>
#include <cstdint>

#define N_NODES 32768
#define N_EDGES 524288
#define NH      4
#define HDIM    128
#define HD      512      // NH*HDIM
#define HID_    128
#define DFF_    2048
#define SLOPE_  0.2f
#define EPS_    1e-5f

// ---------------- scratch (device globals; no allocation allowed) ----------
__device__ float    g_ft [N_NODES*HD];
__device__ float    g_res[N_NODES*HD];
__device__ float    g_el [N_NODES*NH];
__device__ float    g_er [N_NODES*NH];
__device__ float    g_sc [N_EDGES*NH];
__device__ unsigned g_menc[N_NODES*NH];
__device__ float    g_z  [N_NODES*NH];
__device__ int      g_deg[N_NODES];
__device__ int      g_cursor[N_NODES];
__device__ int      g_rowptr[N_NODES+1];
__device__ int      g_eix[N_EDGES];
__device__ float    g_x1 [N_NODES*HID_];

// FFN weights, pre-split hi/lo bf16, transposed to [n][k] tile layout
// W1^T: 32 chunks x [64 n][136 k-padded]   (k = HID 128)
// W2^T: 32 chunks x [128 n][72 k-padded]   (k = DFF chunk 64)
__device__ __align__(16) __nv_bfloat16 g_w1th[32*64*136];
__device__ __align__(16) __nv_bfloat16 g_w1tl[32*64*136];
__device__ __align__(16) __nv_bfloat16 g_w2th[32*128*72];
__device__ __align__(16) __nv_bfloat16 g_w2tl[32*128*72];

// ---------------- warp-mma helpers ------------------------------------------
__device__ __forceinline__ uint32_t smem_u32(const void* p){
    uint32_t a;
    asm("{ .reg .u64 t; cvta.to.shared.u64 t, %1; cvt.u32.u64 %0, t; }" : "=r"(a) : "l"(p));
    return a;
}
__device__ __forceinline__ void ldsm4(unsigned* r, uint32_t addr){
    asm volatile("ldmatrix.sync.aligned.m8n8.x4.shared.b16 {%0,%1,%2,%3}, [%4];"
        : "=r"(r[0]),"=r"(r[1]),"=r"(r[2]),"=r"(r[3]) : "r"(addr));
}
__device__ __forceinline__ void ldsm2(unsigned* r, uint32_t addr){
    asm volatile("ldmatrix.sync.aligned.m8n8.x2.shared.b16 {%0,%1}, [%2];"
        : "=r"(r[0]),"=r"(r[1]) : "r"(addr));
}
__device__ __forceinline__ void mma_bf16(float* c, const unsigned* a, const unsigned* b){
    asm volatile("mma.sync.aligned.m16n8k16.row.col.f32.bf16.bf16.f32 "
        "{%0,%1,%2,%3},{%4,%5,%6,%7},{%8,%9},{%0,%1,%2,%3};"
        : "+f"(c[0]),"+f"(c[1]),"+f"(c[2]),"+f"(c[3])
        : "r"(a[0]),"r"(a[1]),"r"(a[2]),"r"(a[3]),"r"(b[0]),"r"(b[1]));
}

// ordered-float encoding for atomicMax on unsigned
__device__ __forceinline__ unsigned fenc(float f){
    unsigned u = __float_as_uint(f);
    return (u & 0x80000000u) ? ~u : (u | 0x80000000u);
}
__device__ __forceinline__ float fdec(unsigned k){
    return (k & 0x80000000u) ? __uint_as_float(k & 0x7fffffffu)
                             : __uint_as_float(~k);
}

// ---------------- init ------------------------------------------------------
__global__ void k_init(){
    int i = blockIdx.x*256 + threadIdx.x;
    g_z[i]    = 0.f;
    g_menc[i] = 0u;
    if (i < N_NODES){ g_deg[i] = 0; g_cursor[i] = 0; }
}

// ---------------- prep: W1/W2 -> hi/lo bf16 transposed tiles ----------------
__global__ void k_prep(const float* __restrict__ W1, const float* __restrict__ W2){
    int i = blockIdx.x*256 + threadIdx.x;    // 0 .. 262143
    {   // W1 is [k=128][n=2048] row-major
        int k = i >> 11, n = i & 2047;
        float v = W1[i];
        __nv_bfloat16 hv = __float2bfloat16(v);
        __nv_bfloat16 lv = __float2bfloat16(v - __bfloat162float(hv));
        int c = n >> 6, nn = n & 63;
        g_w1th[(c*64+nn)*136 + k] = hv;
        g_w1tl[(c*64+nn)*136 + k] = lv;
    }
    {   // W2 is [k2=2048][n=128] row-major
        int k2 = i >> 7, n = i & 127;
        float v = W2[i];
        __nv_bfloat16 hv = __float2bfloat16(v);
        __nv_bfloat16 lv = __float2bfloat16(v - __bfloat162float(hv));
        int c = k2 >> 6, kk = k2 & 63;
        g_w2th[(c*128+n)*72 + kk] = hv;
        g_w2tl[(c*128+n)*72 + kk] = lv;
    }
}

// ---------------- GEMM A: C[N,512] = h[N,128] @ W[128,512] ------------------
__global__ __launch_bounds__(256) void k_gemmA(const float* __restrict__ h,
        const float* __restrict__ Wfc, const float* __restrict__ Wres){
    __shared__ float As[32][136];
    __shared__ float Bs[32][136];
    const float* __restrict__ W = blockIdx.z ? Wres : Wfc;
    float* __restrict__ C = blockIdx.z ? g_res : g_ft;
    const int row0 = blockIdx.x*128, col0 = blockIdx.y*128;
    const int tid = threadIdx.x, tx = tid & 15, ty = tid >> 4;
    float acc[8][8];
    #pragma unroll
    for (int i=0;i<8;i++)
        #pragma unroll
        for (int j=0;j<8;j++) acc[i][j]=0.f;

    for (int kc=0; kc<HID_; kc+=32){
        #pragma unroll
        for (int j=0;j<4;j++){
            int s = tid + 256*j; int r = s>>3, kq = s&7;
            float4 v = *(const float4*)&h[(row0+r)*HID_ + kc + kq*4];
            As[kq*4+0][r]=v.x; As[kq*4+1][r]=v.y; As[kq*4+2][r]=v.z; As[kq*4+3][r]=v.w;
        }
        #pragma unroll
        for (int j=0;j<4;j++){
            int s = tid + 256*j; int k = s>>5, cq = s&31;
            *(float4*)&Bs[k][cq*4] = *(const float4*)&W[(kc+k)*HD + col0 + cq*4];
        }
        __syncthreads();
        #pragma unroll
        for (int k=0;k<32;k++){
            float a[8], b[8];
            *(float4*)&a[0] = *(float4*)&As[k][ty*8];
            *(float4*)&a[4] = *(float4*)&As[k][ty*8+4];
            *(float4*)&b[0] = *(float4*)&Bs[k][tx*8];
            *(float4*)&b[4] = *(float4*)&Bs[k][tx*8+4];
            #pragma unroll
            for (int i=0;i<8;i++)
                #pragma unroll
                for (int j=0;j<8;j++) acc[i][j] = fmaf(a[i], b[j], acc[i][j]);
        }
        __syncthreads();
    }
    #pragma unroll
    for (int i=0;i<8;i++){
        int row = row0 + ty*8 + i;
        float4 v0 = make_float4(acc[i][0],acc[i][1],acc[i][2],acc[i][3]);
        float4 v1 = make_float4(acc[i][4],acc[i][5],acc[i][6],acc[i][7]);
        *(float4*)&C[row*HD + col0 + tx*8    ] = v0;
        *(float4*)&C[row*HD + col0 + tx*8 + 4] = v1;
    }
}

// ---------------- el/er -----------------------------------------------------
__global__ __launch_bounds__(256) void k_eler(const float* __restrict__ attn_l,
                                              const float* __restrict__ attn_r){
    int wid = threadIdx.x>>5, lane = threadIdx.x&31;
    int gw = blockIdx.x*8 + wid;
    int n = gw>>2, hh = gw&3;
    const float4* ft4 = (const float4*)g_ft;
    float4 x  = ft4[n*128 + hh*32 + lane];
    float4 al = ((const float4*)attn_l)[hh*32+lane];
    float4 ar = ((const float4*)attn_r)[hh*32+lane];
    float pl = x.x*al.x + x.y*al.y + x.z*al.z + x.w*al.w;
    float pr = x.x*ar.x + x.y*ar.y + x.z*ar.z + x.w*ar.w;
    #pragma unroll
    for (int off=16; off; off>>=1){
        pl += __shfl_xor_sync(0xffffffffu, pl, off);
        pr += __shfl_xor_sync(0xffffffffu, pr, off);
    }
    if (lane==0){ g_el[n*NH+hh]=pl; g_er[n*NH+hh]=pr; }
}

// ---------------- edge pass 1 ----------------------------------------------
__global__ __launch_bounds__(256) void k_edge1(const float* __restrict__ e,
        const int* __restrict__ src, const int* __restrict__ dst,
        const float* __restrict__ W_fe, const float* __restrict__ attn_e){
    __shared__ float ce[NH];
    int wid = threadIdx.x>>5, lane = threadIdx.x&31;
    if (wid < NH){
        float p = 0.f;
        #pragma unroll
        for (int q=0;q<4;q++){
            int d = lane + q*32;
            p += W_fe[wid*HDIM+d]*attn_e[wid*HDIM+d];
        }
        #pragma unroll
        for (int off=16; off; off>>=1) p += __shfl_xor_sync(0xffffffffu, p, off);
        if (lane==0) ce[wid]=p;
    }
    __syncthreads();
    int ei = blockIdx.x*256 + threadIdx.x;
    if (ei >= N_EDGES) return;
    int s = src[ei], d = dst[ei];
    float ev = e[ei];
    float4 els = ((const float4*)g_el)[s];
    float4 erd = ((const float4*)g_er)[d];
    float sc[4];
    sc[0] = els.x + erd.x + ev*ce[0];
    sc[1] = els.y + erd.y + ev*ce[1];
    sc[2] = els.z + erd.z + ev*ce[2];
    sc[3] = els.w + erd.w + ev*ce[3];
    #pragma unroll
    for (int hh=0;hh<4;hh++){
        float v = sc[hh];
        v = v > 0.f ? v : SLOPE_*v;
        sc[hh] = v;
        atomicMax(&g_menc[d*NH+hh], fenc(v));
    }
    *(float4*)&g_sc[ei*4] = make_float4(sc[0],sc[1],sc[2],sc[3]);
    atomicAdd(&g_deg[d], 1);
}

// ---------------- edge pass 2 ----------------------------------------------
__global__ __launch_bounds__(256) void k_edge2(const int* __restrict__ dst){
    int ei = blockIdx.x*256 + threadIdx.x;
    if (ei >= N_EDGES) return;
    int d = dst[ei];
    uint4 mk = *(const uint4*)&g_menc[d*4];
    float4 sv = *(const float4*)&g_sc[ei*4];
    float w0 = expf(sv.x - fdec(mk.x));
    float w1 = expf(sv.y - fdec(mk.y));
    float w2 = expf(sv.z - fdec(mk.z));
    float w3 = expf(sv.w - fdec(mk.w));
    *(float4*)&g_sc[ei*4] = make_float4(w0,w1,w2,w3);
    atomicAdd(&g_z[d*4+0], w0);
    atomicAdd(&g_z[d*4+1], w1);
    atomicAdd(&g_z[d*4+2], w2);
    atomicAdd(&g_z[d*4+3], w3);
}

// ---------------- CSR scan --------------------------------------------------
__global__ __launch_bounds__(1024) void k_scan(){
    __shared__ int sm[1024];
    int t = threadIdx.x;
    int base = t*32;
    int s = 0;
    #pragma unroll
    for (int i=0;i<32;i++) s += g_deg[base+i];
    sm[t]=s; __syncthreads();
    for (int off=1; off<1024; off<<=1){
        int v = (t>=off)? sm[t-off] : 0;
        __syncthreads();
        if (t>=off) sm[t]+=v;
        __syncthreads();
    }
    int run = sm[t]-s;
    for (int i=0;i<32;i++){ g_rowptr[base+i]=run; run += g_deg[base+i]; }
    if (t==1023) g_rowptr[N_NODES]=run;
}

__global__ __launch_bounds__(256) void k_fill(const int* __restrict__ dst){
    int ei = blockIdx.x*256 + threadIdx.x;
    if (ei >= N_EDGES) return;
    int d = dst[ei];
    int pos = atomicAdd(&g_cursor[d], 1);
    g_eix[g_rowptr[d]+pos] = ei;
}

// ---------------- aggregation ----------------------------------------------
__global__ __launch_bounds__(256) void k_agg(const int* __restrict__ src,
                                             const float* __restrict__ gat_bias){
    int wid = threadIdx.x>>5, lane = threadIdx.x&31;
    int gw = blockIdx.x*8 + wid;
    int n = gw>>2, hh = gw&3;
    int beg = g_rowptr[n], end = g_rowptr[n+1];
    float zz = g_z[n*NH+hh];
    float zi = zz > 0.f ? 1.f/zz : 1.f;
    float4 acc = make_float4(0,0,0,0);
    const float4* ft4 = (const float4*)g_ft;
    for (int i=beg; i<end; i++){
        int ee = g_eix[i];
        float w = g_sc[ee*4+hh];
        int s = src[ee];
        float4 v = ft4[s*128 + hh*32 + lane];
        acc.x = fmaf(w, v.x, acc.x);
        acc.y = fmaf(w, v.y, acc.y);
        acc.z = fmaf(w, v.z, acc.z);
        acc.w = fmaf(w, v.w, acc.w);
    }
    int base = n*HD + hh*HDIM + lane*4;
    float4 r  = *(const float4*)&g_res[base];
    float4 bv = *(const float4*)&gat_bias[hh*HDIM + lane*4];
    float4 o;
    o.x = fmaxf(acc.x*zi + r.x + bv.x, 0.f);
    o.y = fmaxf(acc.y*zi + r.y + bv.y, 0.f);
    o.z = fmaxf(acc.z*zi + r.z + bv.z, 0.f);
    o.w = fmaxf(acc.w*zi + r.w + bv.w, 0.f);
    *(float4*)&g_res[base] = o;
}

// ---------------- MHA GEMM + relu + residual + LN1 -------------------------
__global__ __launch_bounds__(256) void k_mha(const float* __restrict__ Wm,
        const float* __restrict__ bm, const float* __restrict__ h0,
        const float* __restrict__ g1, const float* __restrict__ be1){
    __shared__ float As[32][136];
    __shared__ float Bs[32][136];
    const int row0 = blockIdx.x*128;
    const int tid = threadIdx.x, tx = tid & 15, ty = tid >> 4;
    float acc[8][8];
    #pragma unroll
    for (int i=0;i<8;i++)
        #pragma unroll
        for (int j=0;j<8;j++) acc[i][j]=0.f;

    for (int kc=0; kc<HD; kc+=32){
        #pragma unroll
        for (int j=0;j<4;j++){
            int s = tid + 256*j; int r = s>>3, kq = s&7;
            float4 v = *(const float4*)&g_res[(row0+r)*HD + kc + kq*4];
            As[kq*4+0][r]=v.x; As[kq*4+1][r]=v.y; As[kq*4+2][r]=v.z; As[kq*4+3][r]=v.w;
        }
        #pragma unroll
        for (int j=0;j<4;j++){
            int s = tid + 256*j; int k = s>>5, cq = s&31;
            *(float4*)&Bs[k][cq*4] = *(const float4*)&Wm[(kc+k)*HID_ + cq*4];
        }
        __syncthreads();
        #pragma unroll
        for (int k=0;k<32;k++){
            float a[8], b[8];
            *(float4*)&a[0] = *(float4*)&As[k][ty*8];
            *(float4*)&a[4] = *(float4*)&As[k][ty*8+4];
            *(float4*)&b[0] = *(float4*)&Bs[k][tx*8];
            *(float4*)&b[4] = *(float4*)&Bs[k][tx*8+4];
            #pragma unroll
            for (int i=0;i<8;i++)
                #pragma unroll
                for (int j=0;j<8;j++) acc[i][j] = fmaf(a[i], b[j], acc[i][j]);
        }
        __syncthreads();
    }
    #pragma unroll
    for (int i=0;i<8;i++){
        int row = row0 + ty*8 + i;
        float v[8], s1=0.f, s2=0.f;
        #pragma unroll
        for (int j=0;j<8;j++){
            int col = tx*8+j;
            float t = acc[i][j] + bm[col];
            t = fmaxf(t, 0.f);
            t += h0[row*HID_+col];
            v[j]=t; s1+=t; s2+=t*t;
        }
        #pragma unroll
        for (int off=8; off; off>>=1){
            s1 += __shfl_xor_sync(0xffffffffu, s1, off, 16);
            s2 += __shfl_xor_sync(0xffffffffu, s2, off, 16);
        }
        float mean = s1*(1.f/HID_);
        float var  = s2*(1.f/HID_) - mean*mean;
        float rs   = rsqrtf(var + EPS_);
        #pragma unroll
        for (int j=0;j<8;j++){
            int col = tx*8+j;
            g_x1[row*HID_+col] = (v[j]-mean)*rs*g1[col] + be1[col];
        }
    }
}

// ---------------- FFN via mma.sync (bf16 hi/lo split) + residual + LN2 ------
// per CTA: 128 rows, DFF chunked by 64. smem (bytes):
#define SM_XS_H 0
#define SM_XS_L 34816
#define SM_W1H  69632
#define SM_W1L  87040
#define SM_W2H  104448
#define SM_W2L  122880
#define SM_MIDH 141312
#define SM_MIDL 159744
#define SMEM_FFN 178176

__global__ __launch_bounds__(256,1) void k_ffn_mma(const float* __restrict__ b1v,
        const float* __restrict__ b2v, const float* __restrict__ g2,
        const float* __restrict__ be2, float* __restrict__ out){
    extern __shared__ char smem[];
    __nv_bfloat16* xs_h = (__nv_bfloat16*)(smem+SM_XS_H);
    __nv_bfloat16* xs_l = (__nv_bfloat16*)(smem+SM_XS_L);
    __nv_bfloat16* mid_h= (__nv_bfloat16*)(smem+SM_MIDH);
    __nv_bfloat16* mid_l= (__nv_bfloat16*)(smem+SM_MIDL);
    const uint32_t sb = smem_u32(smem);
    const int tid = threadIdx.x, lane = tid&31, w = tid>>5;
    const int row0 = blockIdx.x*128, m0 = w*16;

    // stage x tile hi/lo into smem
    for (int i=tid;i<128*128;i+=256){
        int m=i>>7, k=i&127;
        float v = g_x1[(row0+m)*HID_ + k];
        __nv_bfloat16 hv = __float2bfloat16(v);
        xs_h[m*136+k] = hv;
        xs_l[m*136+k] = __float2bfloat16(v - __bfloat162float(hv));
    }

    float acc2[16][4];
    #pragma unroll
    for (int i=0;i<16;i++){ acc2[i][0]=0.f; acc2[i][1]=0.f; acc2[i][2]=0.f; acc2[i][3]=0.f; }

    // ldmatrix lane offsets
    const int a_r = lane & 15;
    const int a_c = (lane & 16) >> 1;   // +8 cols for lanes 16..31
    const int b_r = lane & 7;
    const int b_c = lane & 8;           // +8 cols for lanes 8..15
    const int q = lane & 3, gq = lane >> 2;

    for (int c=0; c<32; c++){
        __syncthreads();   // prior GEMM2 reads of w2/mid done
        {   // copy weight chunk tiles hi/lo
            const uint4* s1h = (const uint4*)(g_w1th + c*64*136);
            const uint4* s1l = (const uint4*)(g_w1tl + c*64*136);
            const uint4* s2h = (const uint4*)(g_w2th + c*128*72);
            const uint4* s2l = (const uint4*)(g_w2tl + c*128*72);
            uint4* t1h = (uint4*)(smem+SM_W1H); uint4* t1l = (uint4*)(smem+SM_W1L);
            uint4* t2h = (uint4*)(smem+SM_W2H); uint4* t2l = (uint4*)(smem+SM_W2L);
            for (int i=tid;i<1088;i+=256){ t1h[i]=s1h[i]; t1l[i]=s1l[i]; }
            for (int i=tid;i<1152;i+=256){ t2h[i]=s2h[i]; t2l[i]=s2l[i]; }
        }
        __syncthreads();

        // GEMM1: mid[128x64] = xs[128x128] @ W1c^T, 3-term split
        float acc1[8][4];
        #pragma unroll
        for (int i=0;i<8;i++){ acc1[i][0]=0.f; acc1[i][1]=0.f; acc1[i][2]=0.f; acc1[i][3]=0.f; }
        #pragma unroll
        for (int kk=0;kk<8;kk++){
            const int k0 = kk*16;
            uint32_t aaddr = sb + SM_XS_H + ((m0+a_r)*136 + k0 + a_c)*2;
            unsigned ah[4], al[4];
            ldsm4(ah, aaddr);
            ldsm4(al, aaddr + (SM_XS_L - SM_XS_H));
            unsigned bh[8][2], bl[8][2];
            #pragma unroll
            for (int nt=0;nt<8;nt++){
                uint32_t baddr = sb + SM_W1H + ((nt*8+b_r)*136 + k0 + b_c)*2;
                ldsm2(bh[nt], baddr);
                ldsm2(bl[nt], baddr + (SM_W1L - SM_W1H));
            }
            #pragma unroll
            for (int nt=0;nt<8;nt++){
                mma_bf16(acc1[nt], ah, bh[nt]);
                mma_bf16(acc1[nt], ah, bl[nt]);
                mma_bf16(acc1[nt], al, bh[nt]);
            }
        }
        // epilogue1: +b1, relu, hi/lo split -> mid
        {
            const int r1 = m0 + gq, r2 = r1 + 8;
            #pragma unroll
            for (int nt=0;nt<8;nt++){
                int col = nt*8 + q*2;
                float bb0 = b1v[c*64+col], bb1 = b1v[c*64+col+1];
                float v0 = fmaxf(acc1[nt][0]+bb0, 0.f);
                float v1 = fmaxf(acc1[nt][1]+bb1, 0.f);
                float v2 = fmaxf(acc1[nt][2]+bb0, 0.f);
                float v3 = fmaxf(acc1[nt][3]+bb1, 0.f);
                __nv_bfloat162 hh, ll;
                hh.x=__float2bfloat16(v0); hh.y=__float2bfloat16(v1);
                ll.x=__float2bfloat16(v0-__bfloat162float(hh.x));
                ll.y=__float2bfloat16(v1-__bfloat162float(hh.y));
                *(__nv_bfloat162*)&mid_h[r1*72+col]=hh;
                *(__nv_bfloat162*)&mid_l[r1*72+col]=ll;
                hh.x=__float2bfloat16(v2); hh.y=__float2bfloat16(v3);
                ll.x=__float2bfloat16(v2-__bfloat162float(hh.x));
                ll.y=__float2bfloat16(v3-__bfloat162float(hh.y));
                *(__nv_bfloat162*)&mid_h[r2*72+col]=hh;
                *(__nv_bfloat162*)&mid_l[r2*72+col]=ll;
            }
        }
        __syncthreads();

        // GEMM2: acc2[128x128] += mid[128x64] @ W2c^T, 3-term split
        #pragma unroll
        for (int kk=0;kk<4;kk++){
            const int k0 = kk*16;
            uint32_t aaddr = sb + SM_MIDH + ((m0+a_r)*72 + k0 + a_c)*2;
            unsigned ah[4], al[4];
            ldsm4(ah, aaddr);
            ldsm4(al, aaddr + (SM_MIDL - SM_MIDH));
            #pragma unroll
            for (int nt=0;nt<16;nt++){
                uint32_t baddr = sb + SM_W2H + ((nt*8+b_r)*72 + k0 + b_c)*2;
                unsigned bh[2], bl[2];
                ldsm2(bh, baddr);
                ldsm2(bl, baddr + (SM_W2L - SM_W2H));
                mma_bf16(acc2[nt], ah, bh);
                mma_bf16(acc2[nt], ah, bl);
                mma_bf16(acc2[nt], al, bh);
            }
        }
    }

    // final epilogue: +b2 + residual + LN2
    #pragma unroll
    for (int half=0; half<2; half++){
        int r = m0 + gq + half*8;
        int grow = row0 + r;
        float tv[32], s1=0.f, s2=0.f;
        #pragma unroll
        for (int nt=0;nt<16;nt++){
            int col = nt*8 + q*2;
            float t0 = acc2[nt][half*2+0] + b2v[col]   + g_x1[grow*HID_+col];
            float t1 = acc2[nt][half*2+1] + b2v[col+1] + g_x1[grow*HID_+col+1];
            tv[nt*2]=t0; tv[nt*2+1]=t1;
            s1 += t0+t1; s2 += t0*t0+t1*t1;
        }
        s1 += __shfl_xor_sync(0xffffffffu, s1, 1); s2 += __shfl_xor_sync(0xffffffffu, s2, 1);
        s1 += __shfl_xor_sync(0xffffffffu, s1, 2); s2 += __shfl_xor_sync(0xffffffffu, s2, 2);
        float mean = s1*(1.f/HID_);
        float var  = s2*(1.f/HID_) - mean*mean;
        float rs   = rsqrtf(var + EPS_);
        #pragma unroll
        for (int nt=0;nt<16;nt++){
            int col = nt*8 + q*2;
            out[grow*HID_+col]   = (tv[nt*2]  -mean)*rs*g2[col]   + be2[col];
            out[grow*HID_+col+1] = (tv[nt*2+1]-mean)*rs*g2[col+1] + be2[col+1];
        }
    }
}

// ---------------- launch ----------------------------------------------------
extern "C" void kernel_launch(void* const* d_in, const int* in_sizes, int n_in,
                              void* d_out, int out_size){
    int o = (in_sizes[4] == 1) ? 1 : 0;
    const float* h       = (const float*)d_in[0];
    const float* e       = (const float*)d_in[1];
    const int*   src     = (const int*)  d_in[2];
    const int*   dst     = (const int*)  d_in[3];
    const float* W_fc    = (const float*)d_in[4+o];
    const float* attn_l  = (const float*)d_in[5+o];
    const float* attn_r  = (const float*)d_in[6+o];
    const float* W_fe    = (const float*)d_in[7+o];
    const float* attn_e  = (const float*)d_in[8+o];
    const float* W_res   = (const float*)d_in[9+o];
    const float* gatb    = (const float*)d_in[10+o];
    const float* W_mha   = (const float*)d_in[11+o];
    const float* b_mha   = (const float*)d_in[12+o];
    const float* n1_g    = (const float*)d_in[13+o];
    const float* n1_b    = (const float*)d_in[14+o];
    const float* n2_g    = (const float*)d_in[15+o];
    const float* n2_b    = (const float*)d_in[16+o];
    const float* W1      = (const float*)d_in[17+o];
    const float* b1      = (const float*)d_in[18+o];
    const float* W2      = (const float*)d_in[19+o];
    const float* b2      = (const float*)d_in[20+o];
    float* out = (float*)d_out;

    cudaFuncSetAttribute(k_ffn_mma, cudaFuncAttributeMaxDynamicSharedMemorySize, SMEM_FFN);

    k_init<<<512,256>>>();
    k_prep<<<1024,256>>>(W1, W2);
    dim3 gA(N_NODES/128, HD/128, 2);
    k_gemmA<<<gA,256>>>(h, W_fc, W_res);
    k_eler<<<N_NODES*NH/8,256>>>(attn_l, attn_r);
    k_edge1<<<N_EDGES/256,256>>>(e, src, dst, W_fe, attn_e);
    k_edge2<<<N_EDGES/256,256>>>(dst);
    k_scan<<<1,1024>>>();
    k_fill<<<N_EDGES/256,256>>>(dst);
    k_agg<<<N_NODES*NH/8,256>>>(src, gatb);
    k_mha<<<N_NODES/128,256>>>(W_mha, b_mha, h, n1_g, n1_b);
    k_ffn_mma<<<N_NODES/128,256,SMEM_FFN>>>(b1, b2, n2_g, n2_b, out);
}

// round 4
// speedup vs baseline: 2.1156x; 1.1652x over previous
#include <cuda_runtime.h>
#include <cuda_bf16.h>
#include <cstdint>

#define N_NODES 32768
#define N_EDGES 524288
#define NH      4
#define HDIM    128
#define HD      512      // NH*HDIM
#define HID_    128
#define DFF_    2048
#define SLOPE_  0.2f
#define EPS_    1e-5f

// ---------------- scratch (device globals; no allocation allowed) ----------
__device__ float    g_ft [N_NODES*HD];
__device__ float    g_res[N_NODES*HD];
__device__ float    g_el [N_NODES*NH];
__device__ float    g_er [N_NODES*NH];
__device__ float    g_sc [N_EDGES*NH];
__device__ unsigned g_menc[N_NODES*NH];
__device__ float    g_z  [N_NODES*NH];
__device__ int      g_deg[N_NODES];
__device__ int      g_cursor[N_NODES];
__device__ int      g_rowptr[N_NODES+1];
__device__ int      g_eix[N_EDGES];
__device__ float    g_x1 [N_NODES*HID_];

// pre-split hi/lo bf16 transposed weights ([n][k] padded rows)
__device__ __align__(16) __nv_bfloat16 g_w1th[32*64*136];
__device__ __align__(16) __nv_bfloat16 g_w1tl[32*64*136];
__device__ __align__(16) __nv_bfloat16 g_w2th[32*128*72];
__device__ __align__(16) __nv_bfloat16 g_w2tl[32*128*72];
__device__ __align__(16) __nv_bfloat16 g_wfth[512*136];   // W_fc^T
__device__ __align__(16) __nv_bfloat16 g_wftl[512*136];
__device__ __align__(16) __nv_bfloat16 g_wrth[512*136];   // W_res^T
__device__ __align__(16) __nv_bfloat16 g_wrtl[512*136];
__device__ __align__(16) __nv_bfloat16 g_wmth[512*136];   // W_mha^T (4 chunks x 128n x 136k)
__device__ __align__(16) __nv_bfloat16 g_wmtl[512*136];

// ---------------- warp-mma helpers ------------------------------------------
__device__ __forceinline__ uint32_t smem_u32(const void* p){
    uint32_t a;
    asm("{ .reg .u64 t; cvta.to.shared.u64 t, %1; cvt.u32.u64 %0, t; }" : "=r"(a) : "l"(p));
    return a;
}
__device__ __forceinline__ void ldsm4(unsigned* r, uint32_t addr){
    asm volatile("ldmatrix.sync.aligned.m8n8.x4.shared.b16 {%0,%1,%2,%3}, [%4];"
        : "=r"(r[0]),"=r"(r[1]),"=r"(r[2]),"=r"(r[3]) : "r"(addr));
}
__device__ __forceinline__ void ldsm2(unsigned* r, uint32_t addr){
    asm volatile("ldmatrix.sync.aligned.m8n8.x2.shared.b16 {%0,%1}, [%2];"
        : "=r"(r[0]),"=r"(r[1]) : "r"(addr));
}
__device__ __forceinline__ void mma_bf16(float* c, const unsigned* a, const unsigned* b){
    asm volatile("mma.sync.aligned.m16n8k16.row.col.f32.bf16.bf16.f32 "
        "{%0,%1,%2,%3},{%4,%5,%6,%7},{%8,%9},{%0,%1,%2,%3};"
        : "+f"(c[0]),"+f"(c[1]),"+f"(c[2]),"+f"(c[3])
        : "r"(a[0]),"r"(a[1]),"r"(a[2]),"r"(a[3]),"r"(b[0]),"r"(b[1]));
}
__device__ __forceinline__ void bsplit(float v, __nv_bfloat16& hi, __nv_bfloat16& lo){
    hi = __float2bfloat16(v);
    lo = __float2bfloat16(v - __bfloat162float(hi));
}

// ordered-float encoding for atomicMax on unsigned
__device__ __forceinline__ unsigned fenc(float f){
    unsigned u = __float_as_uint(f);
    return (u & 0x80000000u) ? ~u : (u | 0x80000000u);
}
__device__ __forceinline__ float fdec(unsigned k){
    return (k & 0x80000000u) ? __uint_as_float(k & 0x7fffffffu)
                             : __uint_as_float(~k);
}

// ---------------- init ------------------------------------------------------
__global__ void k_init(){
    int i = blockIdx.x*256 + threadIdx.x;
    g_z[i]    = 0.f;
    g_menc[i] = 0u;
    if (i < N_NODES){ g_deg[i] = 0; g_cursor[i] = 0; }
}

// ---------------- prep: weights -> hi/lo bf16 transposed tiles --------------
__global__ void k_prep(const float* __restrict__ W1, const float* __restrict__ W2,
                       const float* __restrict__ Wfc, const float* __restrict__ Wres,
                       const float* __restrict__ Wm){
    int i = blockIdx.x*256 + threadIdx.x;    // 0 .. 262143
    {   // W1 [k=128][n=2048]
        int k = i >> 11, n = i & 2047;
        __nv_bfloat16 hv, lv; bsplit(W1[i], hv, lv);
        int c = n >> 6, nn = n & 63;
        g_w1th[(c*64+nn)*136 + k] = hv;
        g_w1tl[(c*64+nn)*136 + k] = lv;
    }
    {   // W2 [k2=2048][n=128]
        int k2 = i >> 7, n = i & 127;
        __nv_bfloat16 hv, lv; bsplit(W2[i], hv, lv);
        int c = k2 >> 6, kk = k2 & 63;
        g_w2th[(c*128+n)*72 + kk] = hv;
        g_w2tl[(c*128+n)*72 + kk] = lv;
    }
    if (i < 65536){
        {   // Wfc/Wres [k=128][n=512]
            int k = i >> 9, n = i & 511;
            __nv_bfloat16 hv, lv;
            bsplit(Wfc[i], hv, lv);
            g_wfth[n*136 + k] = hv; g_wftl[n*136 + k] = lv;
            bsplit(Wres[i], hv, lv);
            g_wrth[n*136 + k] = hv; g_wrtl[n*136 + k] = lv;
        }
        {   // Wm [k2=512][n=128] -> chunk-major [c][n][136]
            int k2 = i >> 7, n = i & 127;
            __nv_bfloat16 hv, lv; bsplit(Wm[i], hv, lv);
            int c = k2 >> 7, kk = k2 & 127;
            g_wmth[(c*128+n)*136 + kk] = hv;
            g_wmtl[(c*128+n)*136 + kk] = lv;
        }
    }
}

// ---------------- GEMM A via mma: {g_ft,g_res}[N,512] = h @ W ---------------
// grid (64, 4, 2): x=rowgroup(4 rowtiles), y=coltile, z=weight select
#define GA_AH 0
#define GA_AL 34816
#define GA_BH 69632
#define GA_BL 104448
#define SMEM_GA 139264

__global__ __launch_bounds__(256,1) void k_gemmA_mma(const float* __restrict__ h){
    extern __shared__ char smem[];
    __nv_bfloat16* ah_s = (__nv_bfloat16*)(smem+GA_AH);
    __nv_bfloat16* al_s = (__nv_bfloat16*)(smem+GA_AL);
    const uint32_t sb = smem_u32(smem);
    const int tid = threadIdx.x, lane = tid&31, w = tid>>5;
    const int m0 = w*16, col0 = blockIdx.y*128;
    const __nv_bfloat16* Bh = blockIdx.z ? g_wrth : g_wfth;
    const __nv_bfloat16* Bl = blockIdx.z ? g_wrtl : g_wftl;
    float* __restrict__ C = blockIdx.z ? g_res : g_ft;

    {   // load B tile (rows col0..col0+127 contiguous)
        const uint4* sh = (const uint4*)(Bh + col0*136);
        const uint4* sl = (const uint4*)(Bl + col0*136);
        uint4* th = (uint4*)(smem+GA_BH);
        uint4* tl = (uint4*)(smem+GA_BL);
        #pragma unroll
        for (int q=0;q<9;q++){
            int i = tid + q*256;
            if (i < 2176){ th[i]=sh[i]; tl[i]=sl[i]; }
        }
    }

    const int a_r = lane & 15, a_c = (lane & 16) >> 1;
    const int b_r = lane & 7,  b_c = lane & 8;
    const int q = lane & 3, gq = lane >> 2;

    for (int rt=0; rt<4; rt++){
        const int row0 = (blockIdx.x*4+rt)*128;
        __syncthreads();
        // stage A hi/lo
        for (int i=tid;i<4096;i+=256){
            int m = i>>5, k4 = (i&31)*4;
            float4 v = *(const float4*)&h[(row0+m)*HID_ + k4];
            __nv_bfloat162 hh, ll;
            bsplit(v.x, hh.x, ll.x); bsplit(v.y, hh.y, ll.y);
            *(__nv_bfloat162*)&ah_s[m*136+k4]   = hh;
            *(__nv_bfloat162*)&al_s[m*136+k4]   = ll;
            bsplit(v.z, hh.x, ll.x); bsplit(v.w, hh.y, ll.y);
            *(__nv_bfloat162*)&ah_s[m*136+k4+2] = hh;
            *(__nv_bfloat162*)&al_s[m*136+k4+2] = ll;
        }
        __syncthreads();

        float acc[16][4];
        #pragma unroll
        for (int i=0;i<16;i++){ acc[i][0]=0.f; acc[i][1]=0.f; acc[i][2]=0.f; acc[i][3]=0.f; }
        #pragma unroll
        for (int kk=0;kk<8;kk++){
            const int k0 = kk*16;
            uint32_t aaddr = sb + GA_AH + ((m0+a_r)*136 + k0 + a_c)*2;
            unsigned ahf[4], alf[4];
            ldsm4(ahf, aaddr);
            ldsm4(alf, aaddr + (GA_AL-GA_AH));
            #pragma unroll
            for (int nt=0;nt<16;nt++){
                uint32_t baddr = sb + GA_BH + ((nt*8+b_r)*136 + k0 + b_c)*2;
                unsigned bh[2], bl[2];
                ldsm2(bh, baddr);
                ldsm2(bl, baddr + (GA_BL-GA_BH));
                mma_bf16(acc[nt], ahf, bh);
                mma_bf16(acc[nt], ahf, bl);
                mma_bf16(acc[nt], alf, bh);
            }
        }
        #pragma unroll
        for (int half=0; half<2; half++){
            int row = row0 + m0 + gq + half*8;
            #pragma unroll
            for (int nt=0;nt<16;nt++){
                int col = col0 + nt*8 + q*2;
                *(float2*)&C[row*HD+col] =
                    make_float2(acc[nt][half*2], acc[nt][half*2+1]);
            }
        }
    }
}

// ---------------- el/er -----------------------------------------------------
__global__ __launch_bounds__(256) void k_eler(const float* __restrict__ attn_l,
                                              const float* __restrict__ attn_r){
    int wid = threadIdx.x>>5, lane = threadIdx.x&31;
    int gw = blockIdx.x*8 + wid;
    int n = gw>>2, hh = gw&3;
    const float4* ft4 = (const float4*)g_ft;
    float4 x  = ft4[n*128 + hh*32 + lane];
    float4 al = ((const float4*)attn_l)[hh*32+lane];
    float4 ar = ((const float4*)attn_r)[hh*32+lane];
    float pl = x.x*al.x + x.y*al.y + x.z*al.z + x.w*al.w;
    float pr = x.x*ar.x + x.y*ar.y + x.z*ar.z + x.w*ar.w;
    #pragma unroll
    for (int off=16; off; off>>=1){
        pl += __shfl_xor_sync(0xffffffffu, pl, off);
        pr += __shfl_xor_sync(0xffffffffu, pr, off);
    }
    if (lane==0){ g_el[n*NH+hh]=pl; g_er[n*NH+hh]=pr; }
}

// ---------------- edge pass 1 ----------------------------------------------
__global__ __launch_bounds__(256) void k_edge1(const float* __restrict__ e,
        const int* __restrict__ src, const int* __restrict__ dst,
        const float* __restrict__ W_fe, const float* __restrict__ attn_e){
    __shared__ float ce[NH];
    int wid = threadIdx.x>>5, lane = threadIdx.x&31;
    if (wid < NH){
        float p = 0.f;
        #pragma unroll
        for (int q=0;q<4;q++){
            int d = lane + q*32;
            p += W_fe[wid*HDIM+d]*attn_e[wid*HDIM+d];
        }
        #pragma unroll
        for (int off=16; off; off>>=1) p += __shfl_xor_sync(0xffffffffu, p, off);
        if (lane==0) ce[wid]=p;
    }
    __syncthreads();
    int ei = blockIdx.x*256 + threadIdx.x;
    if (ei >= N_EDGES) return;
    int s = src[ei], d = dst[ei];
    float ev = e[ei];
    float4 els = ((const float4*)g_el)[s];
    float4 erd = ((const float4*)g_er)[d];
    float sc[4];
    sc[0] = els.x + erd.x + ev*ce[0];
    sc[1] = els.y + erd.y + ev*ce[1];
    sc[2] = els.z + erd.z + ev*ce[2];
    sc[3] = els.w + erd.w + ev*ce[3];
    #pragma unroll
    for (int hh=0;hh<4;hh++){
        float v = sc[hh];
        v = v > 0.f ? v : SLOPE_*v;
        sc[hh] = v;
        atomicMax(&g_menc[d*NH+hh], fenc(v));
    }
    *(float4*)&g_sc[ei*4] = make_float4(sc[0],sc[1],sc[2],sc[3]);
    atomicAdd(&g_deg[d], 1);
}

// ---------------- edge pass 2 ----------------------------------------------
__global__ __launch_bounds__(256) void k_edge2(const int* __restrict__ dst){
    int ei = blockIdx.x*256 + threadIdx.x;
    if (ei >= N_EDGES) return;
    int d = dst[ei];
    uint4 mk = *(const uint4*)&g_menc[d*4];
    float4 sv = *(const float4*)&g_sc[ei*4];
    float w0 = expf(sv.x - fdec(mk.x));
    float w1 = expf(sv.y - fdec(mk.y));
    float w2 = expf(sv.z - fdec(mk.z));
    float w3 = expf(sv.w - fdec(mk.w));
    *(float4*)&g_sc[ei*4] = make_float4(w0,w1,w2,w3);
    atomicAdd(&g_z[d*4+0], w0);
    atomicAdd(&g_z[d*4+1], w1);
    atomicAdd(&g_z[d*4+2], w2);
    atomicAdd(&g_z[d*4+3], w3);
}

// ---------------- CSR scan --------------------------------------------------
__global__ __launch_bounds__(1024) void k_scan(){
    __shared__ int sm[1024];
    int t = threadIdx.x;
    int base = t*32;
    int s = 0;
    #pragma unroll
    for (int i=0;i<32;i++) s += g_deg[base+i];
    sm[t]=s; __syncthreads();
    for (int off=1; off<1024; off<<=1){
        int v = (t>=off)? sm[t-off] : 0;
        __syncthreads();
        if (t>=off) sm[t]+=v;
        __syncthreads();
    }
    int run = sm[t]-s;
    for (int i=0;i<32;i++){ g_rowptr[base+i]=run; run += g_deg[base+i]; }
    if (t==1023) g_rowptr[N_NODES]=run;
}

__global__ __launch_bounds__(256) void k_fill(const int* __restrict__ dst){
    int ei = blockIdx.x*256 + threadIdx.x;
    if (ei >= N_EDGES) return;
    int d = dst[ei];
    int pos = atomicAdd(&g_cursor[d], 1);
    g_eix[g_rowptr[d]+pos] = ei;
}

// ---------------- aggregation ----------------------------------------------
__global__ __launch_bounds__(256) void k_agg(const int* __restrict__ src,
                                             const float* __restrict__ gat_bias){
    int wid = threadIdx.x>>5, lane = threadIdx.x&31;
    int gw = blockIdx.x*8 + wid;
    int n = gw>>2, hh = gw&3;
    int beg = g_rowptr[n], end = g_rowptr[n+1];
    float zz = g_z[n*NH+hh];
    float zi = zz > 0.f ? 1.f/zz : 1.f;
    float4 acc = make_float4(0,0,0,0);
    const float4* ft4 = (const float4*)g_ft;
    for (int i=beg; i<end; i++){
        int ee = g_eix[i];
        float w = g_sc[ee*4+hh];
        int s = src[ee];
        float4 v = ft4[s*128 + hh*32 + lane];
        acc.x = fmaf(w, v.x, acc.x);
        acc.y = fmaf(w, v.y, acc.y);
        acc.z = fmaf(w, v.z, acc.z);
        acc.w = fmaf(w, v.w, acc.w);
    }
    int base = n*HD + hh*HDIM + lane*4;
    float4 r  = *(const float4*)&g_res[base];
    float4 bv = *(const float4*)&gat_bias[hh*HDIM + lane*4];
    float4 o;
    o.x = fmaxf(acc.x*zi + r.x + bv.x, 0.f);
    o.y = fmaxf(acc.y*zi + r.y + bv.y, 0.f);
    o.z = fmaxf(acc.z*zi + r.z + bv.z, 0.f);
    o.w = fmaxf(acc.w*zi + r.w + bv.w, 0.f);
    *(float4*)&g_res[base] = o;
}

// ---------------- MHA via mma + relu + residual + LN1 -----------------------
__global__ __launch_bounds__(256,1) void k_mha_mma(const float* __restrict__ bm,
        const float* __restrict__ h0, const float* __restrict__ g1,
        const float* __restrict__ be1){
    extern __shared__ char smem[];
    __nv_bfloat16* ah_s = (__nv_bfloat16*)(smem+GA_AH);
    __nv_bfloat16* al_s = (__nv_bfloat16*)(smem+GA_AL);
    const uint32_t sb = smem_u32(smem);
    const int tid = threadIdx.x, lane = tid&31, w = tid>>5;
    const int m0 = w*16, row0 = blockIdx.x*128;

    const int a_r = lane & 15, a_c = (lane & 16) >> 1;
    const int b_r = lane & 7,  b_c = lane & 8;
    const int q = lane & 3, gq = lane >> 2;

    float acc[16][4];
    #pragma unroll
    for (int i=0;i<16;i++){ acc[i][0]=0.f; acc[i][1]=0.f; acc[i][2]=0.f; acc[i][3]=0.f; }

    for (int c=0; c<4; c++){
        __syncthreads();
        // stage A chunk hi/lo from g_res
        for (int i=tid;i<4096;i+=256){
            int m = i>>5, k4 = (i&31)*4;
            float4 v = *(const float4*)&g_res[(row0+m)*HD + c*128 + k4];
            __nv_bfloat162 hh, ll;
            bsplit(v.x, hh.x, ll.x); bsplit(v.y, hh.y, ll.y);
            *(__nv_bfloat162*)&ah_s[m*136+k4]   = hh;
            *(__nv_bfloat162*)&al_s[m*136+k4]   = ll;
            bsplit(v.z, hh.x, ll.x); bsplit(v.w, hh.y, ll.y);
            *(__nv_bfloat162*)&ah_s[m*136+k4+2] = hh;
            *(__nv_bfloat162*)&al_s[m*136+k4+2] = ll;
        }
        // copy B chunk (contiguous)
        {
            const uint4* sh = (const uint4*)(g_wmth + c*128*136);
            const uint4* sl = (const uint4*)(g_wmtl + c*128*136);
            uint4* th = (uint4*)(smem+GA_BH);
            uint4* tl = (uint4*)(smem+GA_BL);
            #pragma unroll
            for (int qq=0;qq<9;qq++){
                int i = tid + qq*256;
                if (i < 2176){ th[i]=sh[i]; tl[i]=sl[i]; }
            }
        }
        __syncthreads();
        #pragma unroll
        for (int kk=0;kk<8;kk++){
            const int k0 = kk*16;
            uint32_t aaddr = sb + GA_AH + ((m0+a_r)*136 + k0 + a_c)*2;
            unsigned ahf[4], alf[4];
            ldsm4(ahf, aaddr);
            ldsm4(alf, aaddr + (GA_AL-GA_AH));
            #pragma unroll
            for (int nt=0;nt<16;nt++){
                uint32_t baddr = sb + GA_BH + ((nt*8+b_r)*136 + k0 + b_c)*2;
                unsigned bh[2], bl[2];
                ldsm2(bh, baddr);
                ldsm2(bl, baddr + (GA_BL-GA_BH));
                mma_bf16(acc[nt], ahf, bh);
                mma_bf16(acc[nt], ahf, bl);
                mma_bf16(acc[nt], alf, bh);
            }
        }
    }

    // epilogue: +bm, relu, +h0, LN1 -> g_x1
    #pragma unroll
    for (int half=0; half<2; half++){
        int row = row0 + m0 + gq + half*8;
        float tv[32], s1=0.f, s2=0.f;
        #pragma unroll
        for (int nt=0;nt<16;nt++){
            int col = nt*8 + q*2;
            float t0 = fmaxf(acc[nt][half*2+0] + bm[col],   0.f) + h0[row*HID_+col];
            float t1 = fmaxf(acc[nt][half*2+1] + bm[col+1], 0.f) + h0[row*HID_+col+1];
            tv[nt*2]=t0; tv[nt*2+1]=t1;
            s1 += t0+t1; s2 += t0*t0+t1*t1;
        }
        s1 += __shfl_xor_sync(0xffffffffu, s1, 1); s2 += __shfl_xor_sync(0xffffffffu, s2, 1);
        s1 += __shfl_xor_sync(0xffffffffu, s1, 2); s2 += __shfl_xor_sync(0xffffffffu, s2, 2);
        float mean = s1*(1.f/HID_);
        float var  = s2*(1.f/HID_) - mean*mean;
        float rs   = rsqrtf(var + EPS_);
        #pragma unroll
        for (int nt=0;nt<16;nt++){
            int col = nt*8 + q*2;
            g_x1[row*HID_+col]   = (tv[nt*2]  -mean)*rs*g1[col]   + be1[col];
            g_x1[row*HID_+col+1] = (tv[nt*2+1]-mean)*rs*g1[col+1] + be1[col+1];
        }
    }
}

// ---------------- FFN via mma.sync (bf16 hi/lo split) + residual + LN2 ------
#define SM_XS_H 0
#define SM_XS_L 34816
#define SM_W1H  69632
#define SM_W1L  87040
#define SM_W2H  104448
#define SM_W2L  122880
#define SM_MIDH 141312
#define SM_MIDL 159744
#define SMEM_FFN 178176

__global__ __launch_bounds__(256,1) void k_ffn_mma(const float* __restrict__ b1v,
        const float* __restrict__ b2v, const float* __restrict__ g2,
        const float* __restrict__ be2, float* __restrict__ out){
    extern __shared__ char smem[];
    __nv_bfloat16* xs_h = (__nv_bfloat16*)(smem+SM_XS_H);
    __nv_bfloat16* xs_l = (__nv_bfloat16*)(smem+SM_XS_L);
    __nv_bfloat16* mid_h= (__nv_bfloat16*)(smem+SM_MIDH);
    __nv_bfloat16* mid_l= (__nv_bfloat16*)(smem+SM_MIDL);
    const uint32_t sb = smem_u32(smem);
    const int tid = threadIdx.x, lane = tid&31, w = tid>>5;
    const int row0 = blockIdx.x*128, m0 = w*16;

    for (int i=tid;i<128*128;i+=256){
        int m=i>>7, k=i&127;
        float v = g_x1[(row0+m)*HID_ + k];
        __nv_bfloat16 hv, lv; bsplit(v, hv, lv);
        xs_h[m*136+k] = hv;
        xs_l[m*136+k] = lv;
    }

    float acc2[16][4];
    #pragma unroll
    for (int i=0;i<16;i++){ acc2[i][0]=0.f; acc2[i][1]=0.f; acc2[i][2]=0.f; acc2[i][3]=0.f; }

    const int a_r = lane & 15;
    const int a_c = (lane & 16) >> 1;
    const int b_r = lane & 7;
    const int b_c = lane & 8;
    const int q = lane & 3, gq = lane >> 2;

    for (int c=0; c<32; c++){
        __syncthreads();
        {
            const uint4* s1h = (const uint4*)(g_w1th + c*64*136);
            const uint4* s1l = (const uint4*)(g_w1tl + c*64*136);
            const uint4* s2h = (const uint4*)(g_w2th + c*128*72);
            const uint4* s2l = (const uint4*)(g_w2tl + c*128*72);
            uint4* t1h = (uint4*)(smem+SM_W1H); uint4* t1l = (uint4*)(smem+SM_W1L);
            uint4* t2h = (uint4*)(smem+SM_W2H); uint4* t2l = (uint4*)(smem+SM_W2L);
            for (int i=tid;i<1088;i+=256){ t1h[i]=s1h[i]; t1l[i]=s1l[i]; }
            for (int i=tid;i<1152;i+=256){ t2h[i]=s2h[i]; t2l[i]=s2l[i]; }
        }
        __syncthreads();

        float acc1[8][4];
        #pragma unroll
        for (int i=0;i<8;i++){ acc1[i][0]=0.f; acc1[i][1]=0.f; acc1[i][2]=0.f; acc1[i][3]=0.f; }
        #pragma unroll
        for (int kk=0;kk<8;kk++){
            const int k0 = kk*16;
            uint32_t aaddr = sb + SM_XS_H + ((m0+a_r)*136 + k0 + a_c)*2;
            unsigned ah[4], al[4];
            ldsm4(ah, aaddr);
            ldsm4(al, aaddr + (SM_XS_L - SM_XS_H));
            unsigned bh[8][2], bl[8][2];
            #pragma unroll
            for (int nt=0;nt<8;nt++){
                uint32_t baddr = sb + SM_W1H + ((nt*8+b_r)*136 + k0 + b_c)*2;
                ldsm2(bh[nt], baddr);
                ldsm2(bl[nt], baddr + (SM_W1L - SM_W1H));
            }
            #pragma unroll
            for (int nt=0;nt<8;nt++){
                mma_bf16(acc1[nt], ah, bh[nt]);
                mma_bf16(acc1[nt], ah, bl[nt]);
                mma_bf16(acc1[nt], al, bh[nt]);
            }
        }
        {
            const int r1 = m0 + gq, r2 = r1 + 8;
            #pragma unroll
            for (int nt=0;nt<8;nt++){
                int col = nt*8 + q*2;
                float bb0 = b1v[c*64+col], bb1 = b1v[c*64+col+1];
                float v0 = fmaxf(acc1[nt][0]+bb0, 0.f);
                float v1 = fmaxf(acc1[nt][1]+bb1, 0.f);
                float v2 = fmaxf(acc1[nt][2]+bb0, 0.f);
                float v3 = fmaxf(acc1[nt][3]+bb1, 0.f);
                __nv_bfloat162 hh, ll;
                bsplit(v0, hh.x, ll.x); bsplit(v1, hh.y, ll.y);
                *(__nv_bfloat162*)&mid_h[r1*72+col]=hh;
                *(__nv_bfloat162*)&mid_l[r1*72+col]=ll;
                bsplit(v2, hh.x, ll.x); bsplit(v3, hh.y, ll.y);
                *(__nv_bfloat162*)&mid_h[r2*72+col]=hh;
                *(__nv_bfloat162*)&mid_l[r2*72+col]=ll;
            }
        }
        __syncthreads();

        #pragma unroll
        for (int kk=0;kk<4;kk++){
            const int k0 = kk*16;
            uint32_t aaddr = sb + SM_MIDH + ((m0+a_r)*72 + k0 + a_c)*2;
            unsigned ah[4], al[4];
            ldsm4(ah, aaddr);
            ldsm4(al, aaddr + (SM_MIDL - SM_MIDH));
            #pragma unroll
            for (int nt=0;nt<16;nt++){
                uint32_t baddr = sb + SM_W2H + ((nt*8+b_r)*72 + k0 + b_c)*2;
                unsigned bh[2], bl[2];
                ldsm2(bh, baddr);
                ldsm2(bl, baddr + (SM_W2L - SM_W2H));
                mma_bf16(acc2[nt], ah, bh);
                mma_bf16(acc2[nt], ah, bl);
                mma_bf16(acc2[nt], al, bh);
            }
        }
    }

    #pragma unroll
    for (int half=0; half<2; half++){
        int r = m0 + gq + half*8;
        int grow = row0 + r;
        float tv[32], s1=0.f, s2=0.f;
        #pragma unroll
        for (int nt=0;nt<16;nt++){
            int col = nt*8 + q*2;
            float t0 = acc2[nt][half*2+0] + b2v[col]   + g_x1[grow*HID_+col];
            float t1 = acc2[nt][half*2+1] + b2v[col+1] + g_x1[grow*HID_+col+1];
            tv[nt*2]=t0; tv[nt*2+1]=t1;
            s1 += t0+t1; s2 += t0*t0+t1*t1;
        }
        s1 += __shfl_xor_sync(0xffffffffu, s1, 1); s2 += __shfl_xor_sync(0xffffffffu, s2, 1);
        s1 += __shfl_xor_sync(0xffffffffu, s1, 2); s2 += __shfl_xor_sync(0xffffffffu, s2, 2);
        float mean = s1*(1.f/HID_);
        float var  = s2*(1.f/HID_) - mean*mean;
        float rs   = rsqrtf(var + EPS_);
        #pragma unroll
        for (int nt=0;nt<16;nt++){
            int col = nt*8 + q*2;
            out[grow*HID_+col]   = (tv[nt*2]  -mean)*rs*g2[col]   + be2[col];
            out[grow*HID_+col+1] = (tv[nt*2+1]-mean)*rs*g2[col+1] + be2[col+1];
        }
    }
}

// ---------------- launch ----------------------------------------------------
extern "C" void kernel_launch(void* const* d_in, const int* in_sizes, int n_in,
                              void* d_out, int out_size){
    int o = (in_sizes[4] == 1) ? 1 : 0;
    const float* h       = (const float*)d_in[0];
    const float* e       = (const float*)d_in[1];
    const int*   src     = (const int*)  d_in[2];
    const int*   dst     = (const int*)  d_in[3];
    const float* W_fc    = (const float*)d_in[4+o];
    const float* attn_l  = (const float*)d_in[5+o];
    const float* attn_r  = (const float*)d_in[6+o];
    const float* W_fe    = (const float*)d_in[7+o];
    const float* attn_e  = (const float*)d_in[8+o];
    const float* W_res   = (const float*)d_in[9+o];
    const float* gatb    = (const float*)d_in[10+o];
    const float* W_mha   = (const float*)d_in[11+o];
    const float* b_mha   = (const float*)d_in[12+o];
    const float* n1_g    = (const float*)d_in[13+o];
    const float* n1_b    = (const float*)d_in[14+o];
    const float* n2_g    = (const float*)d_in[15+o];
    const float* n2_b    = (const float*)d_in[16+o];
    const float* W1      = (const float*)d_in[17+o];
    const float* b1      = (const float*)d_in[18+o];
    const float* W2      = (const float*)d_in[19+o];
    const float* b2      = (const float*)d_in[20+o];
    float* out = (float*)d_out;

    cudaFuncSetAttribute(k_ffn_mma,  cudaFuncAttributeMaxDynamicSharedMemorySize, SMEM_FFN);
    cudaFuncSetAttribute(k_gemmA_mma,cudaFuncAttributeMaxDynamicSharedMemorySize, SMEM_GA);
    cudaFuncSetAttribute(k_mha_mma,  cudaFuncAttributeMaxDynamicSharedMemorySize, SMEM_GA);

    k_init<<<512,256>>>();
    k_prep<<<1024,256>>>(W1, W2, W_fc, W_res, W_mha);
    dim3 gA(64, 4, 2);
    k_gemmA_mma<<<gA,256,SMEM_GA>>>(h);
    k_eler<<<N_NODES*NH/8,256>>>(attn_l, attn_r);
    k_edge1<<<N_EDGES/256,256>>>(e, src, dst, W_fe, attn_e);
    k_edge2<<<N_EDGES/256,256>>>(dst);
    k_scan<<<1,1024>>>();
    k_fill<<<N_EDGES/256,256>>>(dst);
    k_agg<<<N_NODES*NH/8,256>>>(src, gatb);
    k_mha_mma<<<N_NODES/128,256,SMEM_GA>>>(b_mha, h, n1_g, n1_b);
    k_ffn_mma<<<N_NODES/128,256,SMEM_FFN>>>(b1, b2, n2_g, n2_b, out);
}